// round 14
// baseline (speedup 1.0000x reference)
#include <cuda_runtime.h>

// AWBM bucket model, single-pass scan. Smem used ONLY to stage/transpose the
// coalesced input into thread-owned order (2 smem ops/element); all compute is
// register-resident in one reused d[8] array (diffs -> excess -> totals), with
// direct global stores. Cross-block: structural collapse of both chains —
//   S-chain: chunk clamp-fn composition saturates (l>=h -> constant) almost
//            surely over 2048 random steps -> S_in from predecessor aggregate
//            alone (walk-back fallback for the unsaturated case).
//   B-chain: chunk affine multiplier m=k^2048 flushes to exactly 0 in fp32 ->
//            B_in(c) = C_{c-1}, no cascade (prod-walk fallback).

#define NTH 256
#define EPT 8
#define CHUNK (NTH * EPT)       // 2048
#define MAX_CHUNKS 4096
#define SIDX(j) ((j) + ((j) >> 5))
#define POS_INF __int_as_float(0x7f800000)
#define NEG_INF __int_as_float(0xff800000)
#define FULL 0xffffffffu

__device__ uint4 g_st1[MAX_CHUNKS];   // {flag, a, l, h}   chunk clamp-fn aggregate
__device__ uint4 g_st2[MAX_CHUNKS];   // {flag, m, c, -}   chunk affine aggregate

struct Fn  { float a, l, h; };        // x -> min(max(x+a, l), h)
struct Aff { float m, c; };           // x -> m*x + c

__device__ __forceinline__ Fn fn_id() { Fn f; f.a = 0.f; f.l = NEG_INF; f.h = POS_INF; return f; }
__device__ __forceinline__ Fn fn_comb(Fn p, Fn n) {   // p applied first
    Fn r;
    r.a = p.a + n.a;
    r.l = fmaxf(p.l + n.a, n.l);
    r.h = fminf(fmaxf(p.h + n.a, n.l), n.h);
    return r;
}
__device__ __forceinline__ float fn_apply(Fn f, float x) {
    return fminf(fmaxf(x + f.a, f.l), f.h);
}
__device__ __forceinline__ Aff af_id() { Aff a; a.m = 1.f; a.c = 0.f; return a; }
__device__ __forceinline__ Aff af_comb(Aff p, Aff n) {
    Aff r; r.m = n.m * p.m; r.c = n.m * p.c + n.c; return r;
}

__device__ __forceinline__ uint4 ldv4(const uint4* p) {
    uint4 v;
    asm volatile("ld.volatile.global.v4.b32 {%0,%1,%2,%3}, [%4];"
                 : "=r"(v.x), "=r"(v.y), "=r"(v.z), "=r"(v.w) : "l"(p) : "memory");
    return v;
}
__device__ __forceinline__ void stv4(uint4* p, uint4 v) {
    asm volatile("st.volatile.global.v4.b32 [%0], {%1,%2,%3,%4};"
                 :: "l"(p), "r"(v.x), "r"(v.y), "r"(v.z), "r"(v.w) : "memory");
}

__global__ void k_reset() {
    int t = blockIdx.x * blockDim.x + threadIdx.x;
    if (t < MAX_CHUNKS) {
        uint4 z; z.x = 0; z.y = 0; z.z = 0; z.w = 0;
        stv4(&g_st1[t], z);
        stv4(&g_st2[t], z);
    }
}

__global__ void __launch_bounds__(NTH)
k_main(const float4* __restrict__ x4, const float2* __restrict__ x2,
       float* __restrict__ out, int T,
       const float* __restrict__ pbfi, const float* __restrict__ pk,
       const float* __restrict__ psmax) {
    __shared__ float sd[SIDX(CHUNK - 1) + 1];
    __shared__ float swa[8], swl[8], swh[8];
    __shared__ float swm[8], swc[8];
    __shared__ float s_bc[2];    // S_in, B_in

    const float bfi = pbfi[0], k = pk[0], smax = psmax[0];
    const float ombfi = 1.f - bfi, omk = 1.f - k;
    const int c = blockIdx.x;
    const int base = c * CHUNK;
    const int nvalid = min(CHUNK, T - base);
    const int tid = threadIdx.x;
    const int lane = tid & 31;
    const int w = tid >> 5;
    const int j0 = tid * EPT;

    // ---- stage diffs in padded smem; zero-fill tail of the partial block ----
    const int n2 = nvalid >> 1;
    for (int i = tid; i < n2; i += NTH) {
        float4 v = x4[(base >> 1) + i];
        sd[SIDX(2 * i)]     = v.x - v.y;
        sd[SIDX(2 * i + 1)] = v.z - v.w;
    }
    if (nvalid < CHUNK) {
        if ((nvalid & 1) && tid == 0) {
            float2 v = x2[base + nvalid - 1];
            sd[SIDX(nvalid - 1)] = v.x - v.y;
        }
        for (int i = nvalid + tid; i < CHUNK; i += NTH)
            sd[SIDX(i)] = 0.f;
    }
    __syncthreads();

    // ---- single smem read pass: my 8 diffs into registers ----
    // EPT=8 divides 32, so SIDX(j0+jj) = SIDX(j0)+jj for jj in [0,8).
    float d[EPT];
    {
        const float* myp = sd + SIDX(j0);
#pragma unroll
        for (int jj = 0; jj < EPT; jj++) d[jj] = myp[jj];
    }

    // ---- 1) per-thread clamp composition (registers, unguarded) ----
    Fn f = fn_id();
#pragma unroll
    for (int jj = 0; jj < EPT; jj++) {
        float dd = d[jj];
        f.a += dd;
        f.l = fmaxf(f.l + dd, 0.f);
        f.h = fminf(fmaxf(f.h + dd, 0.f), smax);
    }

    // ---- 2) warp inclusive scan (shuffle) ----
    Fn finc = f;
#pragma unroll
    for (int off = 1; off < 32; off <<= 1) {
        Fn up;
        up.a = __shfl_up_sync(FULL, finc.a, off);
        up.l = __shfl_up_sync(FULL, finc.l, off);
        up.h = __shfl_up_sync(FULL, finc.h, off);
        if (lane >= off) finc = fn_comb(up, finc);
    }
    if (lane == 31) { swa[w] = finc.a; swl[w] = finc.l; swh[w] = finc.h; }
    __syncthreads();

    // ---- 3) warp 0: combine warp aggs, publish aggregate, resolve S_in ----
    if (w == 0) {
        Fn wa = fn_id();
        if (lane < 8) { wa.a = swa[lane]; wa.l = swl[lane]; wa.h = swh[lane]; }
        Fn wsc = wa;
#pragma unroll
        for (int off = 1; off < 8; off <<= 1) {
            Fn up;
            up.a = __shfl_up_sync(FULL, wsc.a, off);
            up.l = __shfl_up_sync(FULL, wsc.l, off);
            up.h = __shfl_up_sync(FULL, wsc.h, off);
            if (lane >= off) wsc = fn_comb(up, wsc);
        }
        if (lane < 8) { swa[lane] = wsc.a; swl[lane] = wsc.l; swh[lane] = wsc.h; }
        if (lane == 7) {   // block aggregate
            uint4 s;
            s.x = 1u;
            s.y = __float_as_uint(wsc.a); s.z = __float_as_uint(wsc.l); s.w = __float_as_uint(wsc.h);
            stv4(&g_st1[c], s);
        }
        if (lane == 0) {
            float Sin;
            if (c == 0) {
                Sin = 0.5f;                       // S_init
            } else {
                Fn L = fn_id();
                int j = c - 1;
                for (;;) {
                    uint4 st;
                    do { st = ldv4(&g_st1[j]); } while (st.x == 0u);
                    Fn v;
                    v.a = __uint_as_float(st.y);
                    v.l = __uint_as_float(st.z);
                    v.h = __uint_as_float(st.w);
                    L = fn_comb(v, L);
                    if (L.l >= L.h) { Sin = L.h; break; }
                    if (j == 0)     { Sin = fn_apply(L, 0.5f); break; }
                    j--;
                }
            }
            s_bc[0] = Sin;
        }
    }
    __syncthreads();

    // ---- 4) per-thread start S; excess into d[] + thread affine ----
    float S = s_bc[0];
    {
        Fn wex = fn_id();
        if (w > 0) { wex.a = swa[w - 1]; wex.l = swl[w - 1]; wex.h = swh[w - 1]; }
        Fn lex;
        lex.a = __shfl_up_sync(FULL, finc.a, 1);
        lex.l = __shfl_up_sync(FULL, finc.l, 1);
        lex.h = __shfl_up_sync(FULL, finc.h, 1);
        if (lane == 0) lex = fn_id();
        Fn tex = fn_comb(wex, lex);
        S = fn_apply(tex, S);
    }

    Aff af = af_id();
#pragma unroll
    for (int jj = 0; jj < EPT; jj++) {
        float dd = d[jj];
        S = fmaxf(S + dd, 0.f);
        float e = fmaxf(S - smax, 0.f);
        S -= e;
        d[jj] = e;
        af.c = af.c + bfi * e;
        float bf = omk * af.c; af.c = af.c - bf;
        float bm = omk * af.m; af.m = af.m - bm;
    }

    // ---- 5) warp scan of affines ----
    Aff ainc = af;
#pragma unroll
    for (int off = 1; off < 32; off <<= 1) {
        Aff up;
        up.m = __shfl_up_sync(FULL, ainc.m, off);
        up.c = __shfl_up_sync(FULL, ainc.c, off);
        if (lane >= off) ainc = af_comb(up, ainc);
    }
    if (lane == 31) { swm[w] = ainc.m; swc[w] = ainc.c; }
    __syncthreads();

    // ---- 6) warp 0: combine, publish affine aggregate, resolve B_in ----
    if (w == 0) {
        Aff wa = af_id();
        if (lane < 8) { wa.m = swm[lane]; wa.c = swc[lane]; }
        Aff wsc = wa;
#pragma unroll
        for (int off = 1; off < 8; off <<= 1) {
            Aff up;
            up.m = __shfl_up_sync(FULL, wsc.m, off);
            up.c = __shfl_up_sync(FULL, wsc.c, off);
            if (lane >= off) wsc = af_comb(up, wsc);
        }
        if (lane < 8) { swm[lane] = wsc.m; swc[lane] = wsc.c; }
        if (lane == 7) {
            uint4 s;
            s.x = 1u;
            s.y = __float_as_uint(wsc.m); s.z = __float_as_uint(wsc.c); s.w = 0u;
            stv4(&g_st2[c], s);
        }
        if (lane == 0) {
            float Bin;
            if (c == 0) {
                Bin = 1.0f;                       // B_init
            } else {
                float prod = 1.f, acc = 0.f;
                int j = c - 1;
                for (;;) {
                    uint4 st;
                    do { st = ldv4(&g_st2[j]); } while (st.x == 0u);
                    float mj = __uint_as_float(st.y);
                    float Cj = __uint_as_float(st.z);
                    acc += prod * Cj;
                    prod *= mj;
                    if (prod == 0.f) { Bin = acc; break; }
                    if (j == 0)      { Bin = acc + prod * 1.0f; break; }
                    j--;
                }
            }
            s_bc[1] = Bin;
        }
    }
    __syncthreads();

    // ---- 7) per-thread start B; exact reference replay into d[] ----
    float B = s_bc[1];
    {
        Aff wex = af_id();
        if (w > 0) { wex.m = swm[w - 1]; wex.c = swc[w - 1]; }
        Aff lex;
        lex.m = __shfl_up_sync(FULL, ainc.m, 1);
        lex.c = __shfl_up_sync(FULL, ainc.c, 1);
        if (lane == 0) lex = af_id();
        Aff tex = af_comb(wex, lex);
        B = tex.m * B + tex.c;
    }
#pragma unroll
    for (int jj = 0; jj < EPT; jj++) {
        float e = d[jj];
        float outflow = ombfi * e;
        B = B + bfi * e;
        float baseflow = omk * B;
        B = B - baseflow;
        d[jj] = outflow + baseflow;
    }

    // ---- 8) direct global store from registers (2x STG.128 per thread) ----
    if (j0 + EPT <= nvalid) {
        float4* op = (float4*)(out + base + j0);
        float4 v0, v1;
        v0.x = d[0]; v0.y = d[1]; v0.z = d[2]; v0.w = d[3];
        v1.x = d[4]; v1.y = d[5]; v1.z = d[6]; v1.w = d[7];
        op[0] = v0;
        op[1] = v1;
    } else {
#pragma unroll
        for (int jj = 0; jj < EPT; jj++)
            if (j0 + jj < nvalid) out[base + j0 + jj] = d[jj];
    }
}

extern "C" void kernel_launch(void* const* d_in, const int* in_sizes, int n_in,
                              void* d_out, int out_size) {
    const float4* x4   = (const float4*)d_in[0];
    const float2* x2   = (const float2*)d_in[0];
    const float*  BFI  = (const float*)d_in[1];
    const float*  K    = (const float*)d_in[2];
    const float*  Smax = (const float*)d_in[3];
    float* out = (float*)d_out;

    const int T  = in_sizes[0] / 2;
    const int NC = (T + CHUNK - 1) / CHUNK;   // 3907 for T = 8e6

    k_reset<<<(MAX_CHUNKS + 255) / 256, 256>>>();
    k_main<<<NC, NTH>>>(x4, x2, out, T, BFI, K, Smax);
}

// round 16
// speedup vs baseline: 1.0717x; 1.0717x over previous
#include <cuda_runtime.h>

// AWBM bucket model, single-pass scan. Smem only stages/transposes the input
// (split-half layout: STS.64 stage, LDS.128 read, bank-conflict-free, no
// padding arithmetic); compute is register-resident in d[8]; direct global
// stores. Cross-block: structural collapse of both chains —
//   S-chain: chunk clamp-fn composition saturates (l>=h) almost surely over
//            2048 random steps -> S_in from predecessor aggregate (walk-back
//            fallback for the unsaturated case).
//   B-chain: chunk affine multiplier m=k^2048 flushes to 0 in fp32 ->
//            B_in(c)=C_{c-1}, no cascade (prod-walk fallback).

#define NTH 256
#define EPT 8
#define CHUNK (NTH * EPT)       // 2048
#define MAX_CHUNKS 4096
#define POS_INF __int_as_float(0x7f800000)
#define NEG_INF __int_as_float(0xff800000)
#define FULL 0xffffffffu

__device__ uint4 g_st1[MAX_CHUNKS];   // {flag, a, l, h}
__device__ uint4 g_st2[MAX_CHUNKS];   // {flag, m, c, -}

struct Fn  { float a, l, h; };        // x -> min(max(x+a, l), h)
struct Aff { float m, c; };           // x -> m*x + c

__device__ __forceinline__ Fn fn_id() { Fn f; f.a = 0.f; f.l = NEG_INF; f.h = POS_INF; return f; }
__device__ __forceinline__ Fn fn_comb(Fn p, Fn n) {   // p applied first
    Fn r;
    r.a = p.a + n.a;
    r.l = fmaxf(p.l + n.a, n.l);
    r.h = fminf(fmaxf(p.h + n.a, n.l), n.h);
    return r;
}
__device__ __forceinline__ float fn_apply(Fn f, float x) {
    return fminf(fmaxf(x + f.a, f.l), f.h);
}
__device__ __forceinline__ Aff af_id() { Aff a; a.m = 1.f; a.c = 0.f; return a; }
__device__ __forceinline__ Aff af_comb(Aff p, Aff n) {
    Aff r; r.m = n.m * p.m; r.c = n.m * p.c + n.c; return r;
}

__device__ __forceinline__ uint4 ldv4(const uint4* p) {
    uint4 v;
    asm volatile("ld.volatile.global.v4.b32 {%0,%1,%2,%3}, [%4];"
                 : "=r"(v.x), "=r"(v.y), "=r"(v.z), "=r"(v.w) : "l"(p) : "memory");
    return v;
}
__device__ __forceinline__ void stv4(uint4* p, uint4 v) {
    asm volatile("st.volatile.global.v4.b32 [%0], {%1,%2,%3,%4};"
                 :: "l"(p), "r"(v.x), "r"(v.y), "r"(v.z), "r"(v.w) : "memory");
}

__global__ void k_reset() {
    int t = blockIdx.x * blockDim.x + threadIdx.x;
    if (t < MAX_CHUNKS) {
        uint4 z; z.x = 0; z.y = 0; z.z = 0; z.w = 0;
        stv4(&g_st1[t], z);
        stv4(&g_st2[t], z);
    }
}

__global__ void __launch_bounds__(NTH)
k_main(const float4* __restrict__ x4, const float2* __restrict__ x2,
       float* __restrict__ out, int T,
       const float* __restrict__ pbfi, const float* __restrict__ pk,
       const float* __restrict__ psmax) {
    // split-half staging buffer: A = elems (e&7)<4, B = (e&7)>=4, B offset by
    // 16 words so A/B phases cover disjoint bank halves (conflict-free).
    __shared__ __align__(16) float sbuf[CHUNK + 16];
    __shared__ float swa[8], swl[8], swh[8];
    __shared__ float swm[8], swc[8];
    __shared__ float s_bc[2];    // S_in, B_in
    float* const sA = sbuf;
    float* const sB = sbuf + CHUNK / 2 + 16;

    const float bfi = pbfi[0], k = pk[0], smax = psmax[0];
    const float ombfi = 1.f - bfi, omk = 1.f - k;
    const float kbfi = k * bfi;
    const float k2 = k * k, k4 = k2 * k2, k8 = k4 * k4;   // m = k^EPT
    const int c = blockIdx.x;
    const int base = c * CHUNK;
    const int nvalid = min(CHUNK, T - base);
    const int tid = threadIdx.x;
    const int lane = tid & 31;
    const int w = tid >> 5;
    const int j0 = tid * EPT;

    // ---- stage diffs (split-half layout) ----
    if (nvalid == CHUNK) {
        const float4* xp = x4 + (base >> 1);
#pragma unroll
        for (int it = 0; it < CHUNK / 2 / NTH; it++) {
            int i = tid + it * NTH;              // float2-diff index (elems 2i, 2i+1)
            float4 v = xp[i];
            float2 dd; dd.x = v.x - v.y; dd.y = v.z - v.w;
            float* p = (((i & 3) < 2) ? sA : sB) + (i >> 2) * 4 + ((i & 1) << 1);
            *(float2*)p = dd;
        }
    } else {
        for (int e = tid; e < nvalid; e += NTH) {
            float2 v = x2[base + e];
            int q = e >> 3, r = e & 7;
            (((r < 4) ? sA : sB) + q * 4)[r & 3] = v.x - v.y;
        }
        for (int e = nvalid + tid; e < CHUNK; e += NTH) {
            int q = e >> 3, r = e & 7;
            (((r < 4) ? sA : sB) + q * 4)[r & 3] = 0.f;
        }
    }
    __syncthreads();

    // ---- read my 8 diffs: 2x LDS.128, conflict-free ----
    float d[EPT];
    {
        float4 lo = *(const float4*)(sA + tid * 4);
        float4 hi = *(const float4*)(sB + tid * 4);
        d[0] = lo.x; d[1] = lo.y; d[2] = lo.z; d[3] = lo.w;
        d[4] = hi.x; d[5] = hi.y; d[6] = hi.z; d[7] = hi.w;
    }

    // ---- 1) per-thread clamp composition ----
    Fn f = fn_id();
#pragma unroll
    for (int jj = 0; jj < EPT; jj++) {
        float dd = d[jj];
        f.a += dd;
        f.l = fmaxf(f.l + dd, 0.f);
        f.h = fminf(fmaxf(f.h + dd, 0.f), smax);
    }

    // ---- 2) warp inclusive scan (shuffle) ----
    Fn finc = f;
#pragma unroll
    for (int off = 1; off < 32; off <<= 1) {
        Fn up;
        up.a = __shfl_up_sync(FULL, finc.a, off);
        up.l = __shfl_up_sync(FULL, finc.l, off);
        up.h = __shfl_up_sync(FULL, finc.h, off);
        if (lane >= off) finc = fn_comb(up, finc);
    }
    if (lane == 31) { swa[w] = finc.a; swl[w] = finc.l; swh[w] = finc.h; }
    __syncthreads();

    // ---- 3) warp 0: combine warp aggs, publish aggregate, resolve S_in ----
    if (w == 0) {
        Fn wa = fn_id();
        if (lane < 8) { wa.a = swa[lane]; wa.l = swl[lane]; wa.h = swh[lane]; }
        Fn wsc = wa;
#pragma unroll
        for (int off = 1; off < 8; off <<= 1) {
            Fn up;
            up.a = __shfl_up_sync(FULL, wsc.a, off);
            up.l = __shfl_up_sync(FULL, wsc.l, off);
            up.h = __shfl_up_sync(FULL, wsc.h, off);
            if (lane >= off) wsc = fn_comb(up, wsc);
        }
        if (lane < 8) { swa[lane] = wsc.a; swl[lane] = wsc.l; swh[lane] = wsc.h; }
        if (lane == 7) {   // block aggregate
            uint4 s;
            s.x = 1u;
            s.y = __float_as_uint(wsc.a); s.z = __float_as_uint(wsc.l); s.w = __float_as_uint(wsc.h);
            stv4(&g_st1[c], s);
        }
        if (lane == 0) {
            float Sin;
            if (c == 0) {
                Sin = 0.5f;                       // S_init
            } else {
                Fn L = fn_id();
                int j = c - 1;
                for (;;) {
                    uint4 st;
                    do { st = ldv4(&g_st1[j]); } while (st.x == 0u);
                    Fn v;
                    v.a = __uint_as_float(st.y);
                    v.l = __uint_as_float(st.z);
                    v.h = __uint_as_float(st.w);
                    L = fn_comb(v, L);
                    if (L.l >= L.h) { Sin = L.h; break; }
                    if (j == 0)     { Sin = fn_apply(L, 0.5f); break; }
                    j--;
                }
            }
            s_bc[0] = Sin;
        }
    }
    __syncthreads();

    // ---- 4) per-thread start S; excess into d[]; thread affine c (m = k^8) ----
    float S = s_bc[0];
    {
        Fn wex = fn_id();
        if (w > 0) { wex.a = swa[w - 1]; wex.l = swl[w - 1]; wex.h = swh[w - 1]; }
        Fn lex;
        lex.a = __shfl_up_sync(FULL, finc.a, 1);
        lex.l = __shfl_up_sync(FULL, finc.l, 1);
        lex.h = __shfl_up_sync(FULL, finc.h, 1);
        if (lane == 0) lex = fn_id();
        Fn tex = fn_comb(wex, lex);
        S = fn_apply(tex, S);
    }

    float cc = 0.f;
#pragma unroll
    for (int jj = 0; jj < EPT; jj++) {
        float dd = d[jj];
        S = fmaxf(S + dd, 0.f);
        float e = fmaxf(S - smax, 0.f);
        S -= e;
        d[jj] = e;
        cc = fmaf(k, cc, kbfi * e);   // cc' = k*(cc + bfi*e), m-chain is k^8 const
    }
    Aff af; af.m = k8; af.c = cc;

    // ---- 5) warp scan of affines ----
    Aff ainc = af;
#pragma unroll
    for (int off = 1; off < 32; off <<= 1) {
        Aff up;
        up.m = __shfl_up_sync(FULL, ainc.m, off);
        up.c = __shfl_up_sync(FULL, ainc.c, off);
        if (lane >= off) ainc = af_comb(up, ainc);
    }
    if (lane == 31) { swm[w] = ainc.m; swc[w] = ainc.c; }
    __syncthreads();

    // ---- 6) warp 0: combine, publish affine aggregate, resolve B_in ----
    if (w == 0) {
        Aff wa = af_id();
        if (lane < 8) { wa.m = swm[lane]; wa.c = swc[lane]; }
        Aff wsc = wa;
#pragma unroll
        for (int off = 1; off < 8; off <<= 1) {
            Aff up;
            up.m = __shfl_up_sync(FULL, wsc.m, off);
            up.c = __shfl_up_sync(FULL, wsc.c, off);
            if (lane >= off) wsc = af_comb(up, wsc);
        }
        if (lane < 8) { swm[lane] = wsc.m; swc[lane] = wsc.c; }
        if (lane == 7) {
            uint4 s;
            s.x = 1u;
            s.y = __float_as_uint(wsc.m); s.z = __float_as_uint(wsc.c); s.w = 0u;
            stv4(&g_st2[c], s);
        }
        if (lane == 0) {
            float Bin;
            if (c == 0) {
                Bin = 1.0f;                       // B_init
            } else {
                float prod = 1.f, acc = 0.f;
                int j = c - 1;
                for (;;) {
                    uint4 st;
                    do { st = ldv4(&g_st2[j]); } while (st.x == 0u);
                    float mj = __uint_as_float(st.y);
                    float Cj = __uint_as_float(st.z);
                    acc += prod * Cj;
                    prod *= mj;
                    if (prod == 0.f) { Bin = acc; break; }
                    if (j == 0)      { Bin = acc + prod * 1.0f; break; }
                    j--;
                }
            }
            s_bc[1] = Bin;
        }
    }
    __syncthreads();

    // ---- 7) per-thread start B; exact reference replay into d[] ----
    float B = s_bc[1];
    {
        Aff wex = af_id();
        if (w > 0) { wex.m = swm[w - 1]; wex.c = swc[w - 1]; }
        Aff lex;
        lex.m = __shfl_up_sync(FULL, ainc.m, 1);
        lex.c = __shfl_up_sync(FULL, ainc.c, 1);
        if (lane == 0) lex = af_id();
        Aff tex = af_comb(wex, lex);
        B = tex.m * B + tex.c;
    }
#pragma unroll
    for (int jj = 0; jj < EPT; jj++) {
        float e = d[jj];
        float outflow = ombfi * e;
        B = B + bfi * e;
        float baseflow = omk * B;
        B = B - baseflow;
        d[jj] = outflow + baseflow;
    }

    // ---- 8) direct global store from registers (2x STG.128) ----
    if (j0 + EPT <= nvalid) {
        float4* op = (float4*)(out + base + j0);
        float4 v0, v1;
        v0.x = d[0]; v0.y = d[1]; v0.z = d[2]; v0.w = d[3];
        v1.x = d[4]; v1.y = d[5]; v1.z = d[6]; v1.w = d[7];
        op[0] = v0;
        op[1] = v1;
    } else {
#pragma unroll
        for (int jj = 0; jj < EPT; jj++)
            if (j0 + jj < nvalid) out[base + j0 + jj] = d[jj];
    }
}

extern "C" void kernel_launch(void* const* d_in, const int* in_sizes, int n_in,
                              void* d_out, int out_size) {
    const float4* x4   = (const float4*)d_in[0];
    const float2* x2   = (const float2*)d_in[0];
    const float*  BFI  = (const float*)d_in[1];
    const float*  K    = (const float*)d_in[2];
    const float*  Smax = (const float*)d_in[3];
    float* out = (float*)d_out;

    const int T  = in_sizes[0] / 2;
    const int NC = (T + CHUNK - 1) / CHUNK;   // 3907 for T = 8e6

    k_reset<<<(MAX_CHUNKS + 255) / 256, 256>>>();
    k_main<<<NC, NTH>>>(x4, x2, out, T, BFI, K, Smax);
}